// round 10
// baseline (speedup 1.0000x reference)
#include <cuda_runtime.h>
#include <cuda_fp16.h>
#include <cstdint>

// ---------------------------------------------------------------------------
// SimplifiedMamba2Block on GB300 (sm_103a), compute_103-safe.
// Round 9: compat tensor pipe (rt~64cyc/HMMA/SMSP = 2x FMA pipe) is the
// roofline -> make pipes additive via TWO CONCURRENT KERNELS (fork/join
// streams inside the graph): round-7 tensor GEMM on 75% of N, a lean SIMT
// FFMA GEMM on the other 25%, co-resident on every SM.
// ---------------------------------------------------------------------------

#define NTOK   8192
#define DM     1024
#define DI     1536
#define DS     8
#define NDI2   3072
#define SEQ    2048
#define NB     4

#define TN1    2304     // tensor cols for GEMM1 (ffma: 2304..3071)
#define TN2    768      // tensor cols for GEMM2 (ffma: 768..1023)

#define CLIP5(v) fminf(fmaxf((v), -5.0f), 5.0f)

// scratch (__device__ globals per allocation-free rule)
__device__ __half g_xnorm[NTOK * DM];    // LN(x), fp16
__device__ __half g_xh   [NTOK * DI];    // GEMM1 out ssm half, fp16
__device__ __half g_gh   [NTOK * DI];    // GEMM1 out tanh gate, fp16
__device__ __half g_y    [NTOK * DI];    // scan out y*gate, fp16 (GEMM2 A)
__device__ float  g_out1 [NTOK * DM];    // GEMM2 out, fp32
__device__ __half g_win  [NDI2 * DM];    // fp16 W_in
__device__ __half g_wout [DM * DI];      // fp16 W_out

// ======================= helpers ===========================================
__device__ __forceinline__ uint32_t smem_u32(const void* p) {
    uint32_t r;
    asm("{ .reg .u64 t; cvta.to.shared.u64 t, %1; cvt.u32.u64 %0, t; }"
        : "=r"(r) : "l"(p));
    return r;
}
__device__ __forceinline__ void cp_async16(uint32_t saddr, const void* gaddr) {
    asm volatile("cp.async.cg.shared.global [%0], [%1], 16;"
                 :: "r"(saddr), "l"(gaddr) : "memory");
}
#define CP_COMMIT() asm volatile("cp.async.commit_group;" ::: "memory")
#define CP_WAIT(n)  asm volatile("cp.async.wait_group %0;" :: "n"(n) : "memory")

__device__ __forceinline__ void mma_f16(float* d, const uint32_t* a, const uint32_t* b) {
    asm volatile(
        "mma.sync.aligned.m16n8k16.row.col.f32.f16.f16.f32 "
        "{%0,%1,%2,%3}, {%4,%5,%6,%7}, {%8,%9}, {%0,%1,%2,%3};"
        : "+f"(d[0]), "+f"(d[1]), "+f"(d[2]), "+f"(d[3])
        : "r"(a[0]), "r"(a[1]), "r"(a[2]), "r"(a[3]), "r"(b[0]), "r"(b[1]));
}
__device__ __forceinline__ void ldsm_x4(uint32_t* r, uint32_t addr) {
    asm volatile("ldmatrix.sync.aligned.m8n8.x4.shared.b16 {%0,%1,%2,%3}, [%4];"
                 : "=r"(r[0]), "=r"(r[1]), "=r"(r[2]), "=r"(r[3]) : "r"(addr));
}

// ======================= weight prep (fp32 -> fp16) =========================
__global__ __launch_bounds__(256) void prep_w(
    const float* __restrict__ win, const float* __restrict__ wout)
{
    const int n1 = (NDI2 * DM) / 4;
    const int n2 = (DM * DI) / 4;
    int i = blockIdx.x * blockDim.x + threadIdx.x;
    if (i < n1) {
        float4 v = ((const float4*)win)[i];
        __half2 h0 = __floats2half2_rn(v.x, v.y);
        __half2 h1 = __floats2half2_rn(v.z, v.w);
        uint2 u; u.x = *(uint32_t*)&h0; u.y = *(uint32_t*)&h1;
        ((uint2*)g_win)[i] = u;
    } else if (i < n1 + n2) {
        float4 v = ((const float4*)wout)[i - n1];
        __half2 h0 = __floats2half2_rn(v.x, v.y);
        __half2 h1 = __floats2half2_rn(v.z, v.w);
        uint2 u; u.x = *(uint32_t*)&h0; u.y = *(uint32_t*)&h1;
        ((uint2*)g_wout)[i - n1] = u;
    }
}

// ======================= LayerNorm =========================================
template<int HALF_OUT>
__global__ __launch_bounds__(256) void ln_kernel(
    const float* __restrict__ in, const float* __restrict__ g,
    const float* __restrict__ b, void* __restrict__ outv)
{
    __shared__ float s_sum[8], s_sq[8];
    int row = blockIdx.x;
    int tid = threadIdx.x;
    const float4 v = *(const float4*)(in + (size_t)row * DM + tid * 4);

    float sum = v.x + v.y + v.z + v.w;
    float sq  = v.x*v.x + v.y*v.y + v.z*v.z + v.w*v.w;
    #pragma unroll
    for (int o = 16; o > 0; o >>= 1) {
        sum += __shfl_xor_sync(0xffffffffu, sum, o);
        sq  += __shfl_xor_sync(0xffffffffu, sq , o);
    }
    int wid = tid >> 5, lid = tid & 31;
    if (lid == 0) { s_sum[wid] = sum; s_sq[wid] = sq; }
    __syncthreads();
    if (wid == 0) {
        float a = (lid < 8) ? s_sum[lid] : 0.f;
        float c = (lid < 8) ? s_sq [lid] : 0.f;
        #pragma unroll
        for (int o = 4; o > 0; o >>= 1) {
            a += __shfl_xor_sync(0xffffffffu, a, o);
            c += __shfl_xor_sync(0xffffffffu, c, o);
        }
        if (lid == 0) { s_sum[0] = a; s_sq[0] = c; }
    }
    __syncthreads();
    float mean = s_sum[0] * (1.0f / DM);
    float var  = s_sq[0] * (1.0f / DM) - mean * mean;
    float rstd = rsqrtf(var + 1e-5f);

    const float4 gv = *(const float4*)(g + tid * 4);
    const float4 bv = *(const float4*)(b + tid * 4);
    float4 o4;
    o4.x = (v.x - mean) * rstd * gv.x + bv.x;
    o4.y = (v.y - mean) * rstd * gv.y + bv.y;
    o4.z = (v.z - mean) * rstd * gv.z + bv.z;
    o4.w = (v.w - mean) * rstd * gv.w + bv.w;
    if (HALF_OUT) {
        __half2 h0 = __floats2half2_rn(o4.x, o4.y);
        __half2 h1 = __floats2half2_rn(o4.z, o4.w);
        uint2 u; u.x = *(uint32_t*)&h0; u.y = *(uint32_t*)&h1;
        *(uint2*)((__half*)outv + (size_t)row * DM + tid * 4) = u;
    } else {
        *(float4*)((float*)outv + (size_t)row * DM + tid * 4) = o4;
    }
}

// ======================= tensor GEMM (round-7, unchanged) ===================
// C = A @ W^T over cols [0, gridDim.x*BN). 256 thr, 8 warps 4x2, 64x64 warp
// tile, BK=32, 4-stage cp.async ring, ldmatrix fragments.
// MODE 0: clip; col<DI -> fp16 out0h; else tanh -> fp16 out1h
// MODE 1: clip -> fp32 out0f
// ---------------------------------------------------------------------------
#define BM      256
#define BN      128
#define STB     80u
#define A_BYTES (BM * STB)
#define W_BYTES (BN * STB)
#define STAGEB  (A_BYTES + W_BYTES)
#define NSTAGE  4
#define GEMM_SMEM (NSTAGE * STAGEB)     // 122880

template<int MODE>
__global__ __launch_bounds__(256, 1) void mma_gemm(
    const __half* __restrict__ A, const __half* __restrict__ W, int K,
    __half* __restrict__ out0h, __half* __restrict__ out1h,
    float* __restrict__ out0f)
{
    extern __shared__ __align__(16) char dynsmem[];

    const int tid  = threadIdx.x;
    const int lane = tid & 31;
    const int wid  = tid >> 5;
    const int wm   = wid & 3;
    const int wn   = wid >> 2;
    const int bm   = blockIdx.y * BM;
    const int bn   = blockIdx.x * BN;

    float acc[4][8][4];
    #pragma unroll
    for (int mt = 0; mt < 4; mt++)
        #pragma unroll
        for (int nt = 0; nt < 8; nt++)
            #pragma unroll
            for (int f = 0; f < 4; f++) acc[mt][nt][f] = 0.f;

    const int frow = tid >> 2;
    const int fseg = tid & 3;
    const uint32_t sbase = smem_u32(dynsmem);
    const uint32_t fA = (uint32_t)frow * STB + (uint32_t)fseg * 16u;
    const __half* gA = A + (size_t)(bm + frow) * K + fseg * 8;
    const __half* gW = W + (size_t)(bn + frow) * K + fseg * 8;

    const int NC = K / 32;

    const uint32_t laneA = (uint32_t)(lane & 15) * STB + (uint32_t)(lane >> 4) * 16u;
    const uint32_t laneB = (uint32_t)(((lane >> 4) << 3) + (lane & 7)) * STB
                         + (uint32_t)((lane >> 3) & 1) * 16u;

    #pragma unroll
    for (int t = 0; t < 3; t++) {
        uint32_t base = sbase + t * STAGEB;
        const __half* at = gA + t * 32;
        const __half* wt = gW + t * 32;
        #pragma unroll
        for (int k = 0; k < 4; k++)
            cp_async16(base + fA + k * 64u * STB, at + (size_t)(k * 64) * K);
        #pragma unroll
        for (int k = 0; k < 2; k++)
            cp_async16(base + A_BYTES + fA + k * 64u * STB, wt + (size_t)(k * 64) * K);
        CP_COMMIT();
    }

    for (int c = 0; c < NC; c++) {
        if (c + 3 <= NC)      { CP_WAIT(2); }
        else if (c + 2 == NC) { CP_WAIT(1); }
        else                  { CP_WAIT(0); }
        __syncthreads();

        if (c + 3 < NC) {
            uint32_t base = sbase + ((c + 3) & 3) * STAGEB;
            const __half* at = gA + (c + 3) * 32;
            const __half* wt = gW + (c + 3) * 32;
            #pragma unroll
            for (int k = 0; k < 4; k++)
                cp_async16(base + fA + k * 64u * STB, at + (size_t)(k * 64) * K);
            #pragma unroll
            for (int k = 0; k < 2; k++)
                cp_async16(base + A_BYTES + fA + k * 64u * STB, wt + (size_t)(k * 64) * K);
            CP_COMMIT();
        }

        const uint32_t stA = sbase + (c & 3) * STAGEB;
        const uint32_t stW = stA + A_BYTES;

        #pragma unroll
        for (int ks = 0; ks < 2; ks++) {
            const uint32_t kb = (uint32_t)(ks * 32);
            uint32_t a[4][4], b[4][4];
            #pragma unroll
            for (int mt = 0; mt < 4; mt++)
                ldsm_x4(a[mt], stA + (uint32_t)(wm * 64 + mt * 16) * STB + kb + laneA);
            #pragma unroll
            for (int np = 0; np < 4; np++)
                ldsm_x4(b[np], stW + (uint32_t)(wn * 64 + np * 16) * STB + kb + laneB);
            #pragma unroll
            for (int mt = 0; mt < 4; mt++)
                #pragma unroll
                for (int nt = 0; nt < 8; nt++)
                    mma_f16(acc[mt][nt], a[mt], &b[nt >> 1][(nt & 1) * 2]);
        }
    }

    #pragma unroll
    for (int mt = 0; mt < 4; mt++) {
        #pragma unroll
        for (int nt = 0; nt < 8; nt++) {
            const int row0 = bm + wm * 64 + mt * 16 + (lane >> 2);
            const int col  = bn + wn * 64 + nt * 8 + (lane & 3) * 2;
            #pragma unroll
            for (int hh = 0; hh < 2; hh++) {
                const int row = row0 + hh * 8;
                float v0 = CLIP5(acc[mt][nt][hh * 2 + 0]);
                float v1 = CLIP5(acc[mt][nt][hh * 2 + 1]);
                if (MODE == 0) {
                    if (col < DI) {
                        *(__half2*)(out0h + (size_t)row * DI + col) =
                            __floats2half2_rn(v0, v1);
                    } else {
                        *(__half2*)(out1h + (size_t)row * DI + (col - DI)) =
                            __floats2half2_rn(tanhf(v0), tanhf(v1));
                    }
                } else {
                    *(float2*)(out0f + (size_t)row * DM + col) = make_float2(v0, v1);
                }
            }
        }
    }
}

// ======================= SIMT FFMA GEMM (concurrent strip) ==================
// C = A @ Wf^T over cols [n0, n0 + gridDim.x*64). A fp16, Wf ORIGINAL fp32.
// 128 threads, tile 128x64, BK=32, double-buffered (A: LDG+cvt+STS fp32;
// W: cp.async fp32). Microtile 8x8: rows ty*8+i, cols j*8+tx.
// Designed small (55KB smem, ~15K regs) to CO-RESIDE with a tensor CTA.
// MODE 0: all cols >= DI -> tanh -> fp16 outg ; MODE 1: fp32 outf.
// ---------------------------------------------------------------------------
#define FBM     128
#define FBN     64
#define FST     36                      // row stride (floats) for A_s and W_s
#define F_WOFF  (FBM * FST)             // 4608 floats
#define F_STAGEF (FBM * FST + FBN * FST)  // 6912 floats
#define F_SMEM  (2 * F_STAGEF * 4)      // 55296 bytes

#define F_FILL(buf, k0) do {                                                   \
    float* As_ = fsm + (buf) * F_STAGEF;                                       \
    _Pragma("unroll")                                                          \
    for (int q = 0; q < 4; q++) {                                              \
        uint4 raw = *(const uint4*)(gA + (k0) + q * 8);                        \
        __half2* hp = (__half2*)&raw;                                          \
        float2 f0 = __half22float2(hp[0]), f1 = __half22float2(hp[1]);         \
        float2 f2 = __half22float2(hp[2]), f3 = __half22float2(hp[3]);         \
        float* dst = As_ + tid * FST + q * 8;                                  \
        *(float4*)(dst)     = make_float4(f0.x, f0.y, f1.x, f1.y);             \
        *(float4*)(dst + 4) = make_float4(f2.x, f2.y, f3.x, f3.y);             \
    }                                                                          \
    uint32_t sb_ = sbase + (buf) * F_STAGEF * 4;                               \
    _Pragma("unroll")                                                          \
    for (int j = 0; j < 4; j++) cp_async16(sb_ + wdst[j], wsrc[j] + (k0));     \
    CP_COMMIT();                                                               \
} while (0)

template<int MODE>
__global__ __launch_bounds__(128, 1) void ffma_gemm(
    const __half* __restrict__ Ah, const float* __restrict__ Wf, int K, int n0,
    __half* __restrict__ outg, float* __restrict__ outf)
{
    extern __shared__ __align__(16) float fsm[];
    const int tid = threadIdx.x;
    const int tx = tid & 7;            // col lane: cols j*8 + tx
    const int ty = tid >> 3;           // 0..15: rows ty*8 .. +7
    const int bm = blockIdx.y * FBM;
    const int bn = n0 + blockIdx.x * FBN;

    float acc[8][8];
    #pragma unroll
    for (int i = 0; i < 8; i++)
        #pragma unroll
        for (int j = 0; j < 8; j++) acc[i][j] = 0.f;

    const __half* gA = Ah + (size_t)(bm + tid) * K;     // thread fills row tid
    const uint32_t sbase = smem_u32(fsm);

    // W fill: 512 x 16B segs per stage, 4 per thread
    uint32_t wdst[4];
    const float* wsrc[4];
    #pragma unroll
    for (int j = 0; j < 4; j++) {
        int s = tid + j * 128;
        int row = s >> 3, q = s & 7;
        wdst[j] = (uint32_t)((F_WOFF + row * FST + q * 4) * 4);
        wsrc[j] = Wf + (size_t)(bn + row) * K + q * 4;
    }

    const int NC = K / 32;
    F_FILL(0, 0);

    for (int c = 0; c < NC; c++) {
        const int buf = c & 1;
        CP_WAIT(0);
        __syncthreads();
        if (c + 1 < NC) F_FILL(buf ^ 1, (c + 1) * 32);

        const float* As = fsm + buf * F_STAGEF + (ty * 8) * FST;
        const float* Ws = fsm + buf * F_STAGEF + F_WOFF + tx * FST;

        #pragma unroll
        for (int k = 0; k < 32; k += 2) {
            float2 a[8], w[8];
            #pragma unroll
            for (int i = 0; i < 8; i++) a[i] = *(const float2*)&As[i * FST + k];
            #pragma unroll
            for (int j = 0; j < 8; j++) w[j] = *(const float2*)&Ws[j * 8 * FST + k];
            #pragma unroll
            for (int i = 0; i < 8; i++)
                #pragma unroll
                for (int j = 0; j < 8; j++)
                    acc[i][j] = fmaf(a[i].x, w[j].x,
                                 fmaf(a[i].y, w[j].y, acc[i][j]));
        }
    }

    #pragma unroll
    for (int i = 0; i < 8; i++) {
        const int row = bm + ty * 8 + i;
        #pragma unroll
        for (int j = 0; j < 8; j++) {
            const int col = bn + j * 8 + tx;
            float v = CLIP5(acc[i][j]);
            if (MODE == 0)
                outg[(size_t)row * DI + (col - DI)] = __float2half_rn(tanhf(v));
            else
                outf[(size_t)row * DM + col] = v;
        }
    }
}

// ======================= SSM scan (round-7) =================================
__global__ __launch_bounds__(128) void scan_kernel(
    const float* __restrict__ A_log, const float* __restrict__ Bm,
    const float* __restrict__ Cm)
{
    int idx = blockIdx.x * blockDim.x + threadIdx.x;
    int b = idx / DI;
    int i = idx - b * DI;

    float decay[DS], bs[DS], cs[DS], hreg[DS];
    #pragma unroll
    for (int s = 0; s < DS; s++) {
        float a = A_log[i * DS + s];
        a = fminf(fmaxf(a, -5.0f), 0.0f);
        float Av = -__expf(a);
        Av = fminf(fmaxf(Av, -2.0f), -0.01f);
        decay[s] = Av * 0.9f;
        bs[s] = Bm[i * DS + s] * 0.1f;
        cs[s] = Cm[i * DS + s];
        hreg[s] = 0.f;
    }

    const __half* __restrict__ xin  = g_xh + (size_t)b * SEQ * DI + i;
    const __half* __restrict__ gin  = g_gh + (size_t)b * SEQ * DI + i;
    __half*       __restrict__ yout = g_y  + (size_t)b * SEQ * DI + i;

    #pragma unroll 8
    for (int t = 0; t < SEQ; t++) {
        float x  = __half2float(xin[(size_t)t * DI]);
        float gt = __half2float(gin[(size_t)t * DI]);
        float y = 0.f;
        #pragma unroll
        for (int s = 0; s < DS; s++) {
            float hs = fmaf(hreg[s], decay[s], x * bs[s]);
            hs = CLIP5(hs);
            hreg[s] = hs;
            y = fmaf(hs, cs[s], y);
        }
        y = CLIP5(y);
        yout[(size_t)t * DI] = __float2half_rn(y * gt);
    }
}

// ======================= streams (static init: before harness checkpoints) ==
struct HxStreams {
    cudaStream_t s2;
    cudaEvent_t ev[4];
    HxStreams() {
        cudaStreamCreateWithFlags(&s2, cudaStreamNonBlocking);
        for (int i = 0; i < 4; i++)
            cudaEventCreateWithFlags(&ev[i], cudaEventDisableTiming);
    }
};
static HxStreams g_hx;

// ======================= launch =============================================
extern "C" void kernel_launch(void* const* d_in, const int* in_sizes, int n_in,
                              void* d_out, int out_size)
{
    const float* x       = (const float*)d_in[0];
    const float* W_in    = (const float*)d_in[1];
    const float* W_out   = (const float*)d_in[2];
    const float* A_log   = (const float*)d_in[3];
    const float* Bm      = (const float*)d_in[4];
    const float* Cm      = (const float*)d_in[5];
    const float* ln_in_g = (const float*)d_in[6];
    const float* ln_in_b = (const float*)d_in[7];
    const float* ln_out_g= (const float*)d_in[8];
    const float* ln_out_b= (const float*)d_in[9];
    float* out = (float*)d_out;

    __half *p_xnorm, *p_xh, *p_gh, *p_y, *p_win, *p_wout;
    float *p_out1;
    cudaGetSymbolAddress((void**)&p_xnorm, g_xnorm);
    cudaGetSymbolAddress((void**)&p_xh   , g_xh);
    cudaGetSymbolAddress((void**)&p_gh   , g_gh);
    cudaGetSymbolAddress((void**)&p_y    , g_y);
    cudaGetSymbolAddress((void**)&p_out1 , g_out1);
    cudaGetSymbolAddress((void**)&p_win  , g_win);
    cudaGetSymbolAddress((void**)&p_wout , g_wout);

    cudaFuncSetAttribute(mma_gemm<0>, cudaFuncAttributeMaxDynamicSharedMemorySize, GEMM_SMEM);
    cudaFuncSetAttribute(mma_gemm<1>, cudaFuncAttributeMaxDynamicSharedMemorySize, GEMM_SMEM);
    cudaFuncSetAttribute(ffma_gemm<0>, cudaFuncAttributeMaxDynamicSharedMemorySize, F_SMEM);
    cudaFuncSetAttribute(ffma_gemm<1>, cudaFuncAttributeMaxDynamicSharedMemorySize, F_SMEM);

    // 0) weights -> fp16 scratch (tensor strips only; ffma reads fp32 direct)
    {
        int total4 = (NDI2 * DM + DM * DI) / 4;
        prep_w<<<(total4 + 255) / 256, 256>>>(W_in, W_out);
    }

    // 1) input LN -> fp16
    ln_kernel<1><<<NTOK, 256>>>(x, ln_in_g, ln_in_b, p_xnorm);

    // 2) GEMM1 split: tensor cols [0,2304) ; ffma cols [2304,3072) concurrent
    cudaEventRecord(g_hx.ev[0], 0);
    cudaStreamWaitEvent(g_hx.s2, g_hx.ev[0], 0);
    {
        dim3 grid(TN1 / BN, NTOK / BM);                  // (18, 32)
        mma_gemm<0><<<grid, 256, GEMM_SMEM>>>(p_xnorm, p_win, DM, p_xh, p_gh, nullptr);
    }
    {
        dim3 grid((NDI2 - TN1) / FBN, NTOK / FBM);       // (12, 64)
        ffma_gemm<0><<<grid, 128, F_SMEM, g_hx.s2>>>(p_xnorm, W_in, DM, TN1, p_gh, nullptr);
    }
    cudaEventRecord(g_hx.ev[1], g_hx.s2);
    cudaStreamWaitEvent(0, g_hx.ev[1], 0);

    // 3) scan: fp16(y*tanh(gate)) -> g_y
    scan_kernel<<<(NB * DI) / 128, 128>>>(A_log, Bm, Cm);

    // 4) GEMM2 split: tensor cols [0,768) ; ffma cols [768,1024) concurrent
    cudaEventRecord(g_hx.ev[2], 0);
    cudaStreamWaitEvent(g_hx.s2, g_hx.ev[2], 0);
    {
        dim3 grid(TN2 / BN, NTOK / BM);                  // (6, 32)
        mma_gemm<1><<<grid, 256, GEMM_SMEM>>>(p_y, p_wout, DI, nullptr, nullptr, p_out1);
    }
    {
        dim3 grid((DM - TN2) / FBN, NTOK / FBM);         // (4, 64)
        ffma_gemm<1><<<grid, 128, F_SMEM, g_hx.s2>>>(p_y, W_out, DI, TN2, nullptr, p_out1);
    }
    cudaEventRecord(g_hx.ev[3], g_hx.s2);
    cudaStreamWaitEvent(0, g_hx.ev[3], 0);

    // 5) output LN -> fp32 d_out
    ln_kernel<0><<<NTOK, 256>>>(p_out1, ln_out_g, ln_out_b, out);
}

// round 11
// speedup vs baseline: 1.4436x; 1.4436x over previous
#include <cuda_runtime.h>
#include <cuda_fp16.h>
#include <cstdint>

// ---------------------------------------------------------------------------
// SimplifiedMamba2Block on GB300 (sm_103a), compute_103-safe.
// Round 11: R7 tensor GEMM core (proven 1180us) + persistent-CTA tile queue
// (kills wave-quantization tails: 768/148=5.19 and 256/148=1.73 waves) +
// prep_w overlapped with LN_in on a fork stream.
// Model: mma.sync on sm_103a executes on the FMA datapath (~64 MAC/cyc/SMSP);
// R7 core is ~91% of that ceiling, so we attack scheduling losses only.
// ---------------------------------------------------------------------------

#define NTOK   8192
#define DM     1024
#define DI     1536
#define DS     8
#define NDI2   3072
#define SEQ    2048
#define NB     4

#define CLIP5(v) fminf(fmaxf((v), -5.0f), 5.0f)

// scratch (__device__ globals per allocation-free rule)
__device__ __half g_xnorm[NTOK * DM];    // LN(x), fp16
__device__ __half g_xh   [NTOK * DI];    // GEMM1 out ssm half, fp16
__device__ __half g_gh   [NTOK * DI];    // GEMM1 out tanh gate, fp16
__device__ __half g_y    [NTOK * DI];    // scan out y*gate, fp16 (GEMM2 A)
__device__ float  g_out1 [NTOK * DM];    // GEMM2 out, fp32
__device__ __half g_win  [NDI2 * DM];    // fp16 W_in
__device__ __half g_wout [DM * DI];      // fp16 W_out
__device__ int    g_ctr1;                // persistent tile counters
__device__ int    g_ctr2;

// ======================= helpers ===========================================
__device__ __forceinline__ uint32_t smem_u32(const void* p) {
    uint32_t r;
    asm("{ .reg .u64 t; cvta.to.shared.u64 t, %1; cvt.u32.u64 %0, t; }"
        : "=r"(r) : "l"(p));
    return r;
}
__device__ __forceinline__ void cp_async16(uint32_t saddr, const void* gaddr) {
    asm volatile("cp.async.cg.shared.global [%0], [%1], 16;"
                 :: "r"(saddr), "l"(gaddr) : "memory");
}
#define CP_COMMIT() asm volatile("cp.async.commit_group;" ::: "memory")
#define CP_WAIT(n)  asm volatile("cp.async.wait_group %0;" :: "n"(n) : "memory")

__device__ __forceinline__ void mma_f16(float* d, const uint32_t* a, const uint32_t* b) {
    asm volatile(
        "mma.sync.aligned.m16n8k16.row.col.f32.f16.f16.f32 "
        "{%0,%1,%2,%3}, {%4,%5,%6,%7}, {%8,%9}, {%0,%1,%2,%3};"
        : "+f"(d[0]), "+f"(d[1]), "+f"(d[2]), "+f"(d[3])
        : "r"(a[0]), "r"(a[1]), "r"(a[2]), "r"(a[3]), "r"(b[0]), "r"(b[1]));
}
__device__ __forceinline__ void ldsm_x4(uint32_t* r, uint32_t addr) {
    asm volatile("ldmatrix.sync.aligned.m8n8.x4.shared.b16 {%0,%1,%2,%3}, [%4];"
                 : "=r"(r[0]), "=r"(r[1]), "=r"(r[2]), "=r"(r[3]) : "r"(addr));
}

// ======================= weight prep (fp32 -> fp16) =========================
__global__ __launch_bounds__(256) void prep_w(
    const float* __restrict__ win, const float* __restrict__ wout)
{
    const int n1 = (NDI2 * DM) / 4;
    const int n2 = (DM * DI) / 4;
    int i = blockIdx.x * blockDim.x + threadIdx.x;
    if (i < n1) {
        float4 v = ((const float4*)win)[i];
        __half2 h0 = __floats2half2_rn(v.x, v.y);
        __half2 h1 = __floats2half2_rn(v.z, v.w);
        uint2 u; u.x = *(uint32_t*)&h0; u.y = *(uint32_t*)&h1;
        ((uint2*)g_win)[i] = u;
    } else if (i < n1 + n2) {
        float4 v = ((const float4*)wout)[i - n1];
        __half2 h0 = __floats2half2_rn(v.x, v.y);
        __half2 h1 = __floats2half2_rn(v.z, v.w);
        uint2 u; u.x = *(uint32_t*)&h0; u.y = *(uint32_t*)&h1;
        ((uint2*)g_wout)[i - n1] = u;
    }
}

// ======================= LayerNorm =========================================
template<int HALF_OUT>
__global__ __launch_bounds__(256) void ln_kernel(
    const float* __restrict__ in, const float* __restrict__ g,
    const float* __restrict__ b, void* __restrict__ outv)
{
    __shared__ float s_sum[8], s_sq[8];
    int row = blockIdx.x;
    int tid = threadIdx.x;
    const float4 v = *(const float4*)(in + (size_t)row * DM + tid * 4);

    float sum = v.x + v.y + v.z + v.w;
    float sq  = v.x*v.x + v.y*v.y + v.z*v.z + v.w*v.w;
    #pragma unroll
    for (int o = 16; o > 0; o >>= 1) {
        sum += __shfl_xor_sync(0xffffffffu, sum, o);
        sq  += __shfl_xor_sync(0xffffffffu, sq , o);
    }
    int wid = tid >> 5, lid = tid & 31;
    if (lid == 0) { s_sum[wid] = sum; s_sq[wid] = sq; }
    __syncthreads();
    if (wid == 0) {
        float a = (lid < 8) ? s_sum[lid] : 0.f;
        float c = (lid < 8) ? s_sq [lid] : 0.f;
        #pragma unroll
        for (int o = 4; o > 0; o >>= 1) {
            a += __shfl_xor_sync(0xffffffffu, a, o);
            c += __shfl_xor_sync(0xffffffffu, c, o);
        }
        if (lid == 0) { s_sum[0] = a; s_sq[0] = c; }
    }
    __syncthreads();
    float mean = s_sum[0] * (1.0f / DM);
    float var  = s_sq[0] * (1.0f / DM) - mean * mean;
    float rstd = rsqrtf(var + 1e-5f);

    const float4 gv = *(const float4*)(g + tid * 4);
    const float4 bv = *(const float4*)(b + tid * 4);
    float4 o4;
    o4.x = (v.x - mean) * rstd * gv.x + bv.x;
    o4.y = (v.y - mean) * rstd * gv.y + bv.y;
    o4.z = (v.z - mean) * rstd * gv.z + bv.z;
    o4.w = (v.w - mean) * rstd * gv.w + bv.w;
    if (HALF_OUT) {
        __half2 h0 = __floats2half2_rn(o4.x, o4.y);
        __half2 h1 = __floats2half2_rn(o4.z, o4.w);
        uint2 u; u.x = *(uint32_t*)&h0; u.y = *(uint32_t*)&h1;
        *(uint2*)((__half*)outv + (size_t)row * DM + tid * 4) = u;
    } else {
        *(float4*)((float*)outv + (size_t)row * DM + tid * 4) = o4;
    }
}

// ======================= persistent tensor GEMM (256x128 tile) ==============
// C = A @ W^T. A: MxK rm fp16, W: NxK rm fp16. K % 128 == 0 (NC % 4 == 0).
// R7 core: 256 thr, 8 warps 4x2, warp tile 64x64, BK=32, 4-stage cp.async
// ring, ldmatrix fragments. Persistent: grid=148 CTAs (1/SM via 123KB smem)
// pull tiles from an atomic queue -> finish-skew <= 1 tile instead of a
// full wave (768 tiles = 5.19 waves; 256 tiles = 1.73 waves).
// Cross-tile buffer safety: prologue fills ring slots {0,1,2}; with NC%4==0
// the only slot possibly still being read by lagging warps is 3.
// MODE 0: clip; col<DI -> fp16 out0h; else tanh -> fp16 out1h
// MODE 1: clip -> fp32 out0f
// ---------------------------------------------------------------------------
#define BM      256
#define BN      128
#define STB     80u
#define A_BYTES (BM * STB)
#define W_BYTES (BN * STB)
#define STAGEB  (A_BYTES + W_BYTES)
#define NSTAGE  4
#define GEMM_SMEM (NSTAGE * STAGEB)     // 122880
#define NPERS   148

template<int MODE>
__global__ __launch_bounds__(256, 1) void mma_gemm_pers(
    const __half* __restrict__ A, const __half* __restrict__ W, int K,
    int nx, int ntiles, int* __restrict__ ctr,
    __half* __restrict__ out0h, __half* __restrict__ out1h,
    float* __restrict__ out0f)
{
    extern __shared__ __align__(16) char dynsmem[];
    __shared__ int s_tile;

    const int tid  = threadIdx.x;
    const int lane = tid & 31;
    const int wid  = tid >> 5;
    const int wm   = wid & 3;
    const int wn   = wid >> 2;
    const uint32_t sbase = smem_u32(dynsmem);
    const int NC = K / 32;

    const int frow = tid >> 2;
    const int fseg = tid & 3;
    const uint32_t fA = (uint32_t)frow * STB + (uint32_t)fseg * 16u;

    const uint32_t laneA = (uint32_t)(lane & 15) * STB + (uint32_t)(lane >> 4) * 16u;
    const uint32_t laneB = (uint32_t)(((lane >> 4) << 3) + (lane & 7)) * STB
                         + (uint32_t)((lane >> 3) & 1) * 16u;

    while (true) {
        __syncthreads();                       // all warps done with s_tile
        if (tid == 0) s_tile = atomicAdd(ctr, 1);
        __syncthreads();
        const int t = s_tile;
        if (t >= ntiles) break;                // uniform across CTA

        const int bm = (t / nx) * BM;
        const int bn = (t % nx) * BN;
        const __half* gA = A + (size_t)(bm + frow) * K + fseg * 8;
        const __half* gW = W + (size_t)(bn + frow) * K + fseg * 8;

        float acc[4][8][4];
        #pragma unroll
        for (int mt = 0; mt < 4; mt++)
            #pragma unroll
            for (int nt = 0; nt < 8; nt++)
                #pragma unroll
                for (int f = 0; f < 4; f++) acc[mt][nt][f] = 0.f;

        // prologue: stages 0..2 (slot 3 may still be read by lagging warps)
        #pragma unroll
        for (int pt = 0; pt < 3; pt++) {
            uint32_t base = sbase + pt * STAGEB;
            const __half* at = gA + pt * 32;
            const __half* wt = gW + pt * 32;
            #pragma unroll
            for (int k = 0; k < 4; k++)
                cp_async16(base + fA + k * 64u * STB, at + (size_t)(k * 64) * K);
            #pragma unroll
            for (int k = 0; k < 2; k++)
                cp_async16(base + A_BYTES + fA + k * 64u * STB, wt + (size_t)(k * 64) * K);
            CP_COMMIT();
        }

        for (int c = 0; c < NC; c++) {
            if (c + 3 <= NC)      { CP_WAIT(2); }
            else if (c + 2 == NC) { CP_WAIT(1); }
            else                  { CP_WAIT(0); }
            __syncthreads();

            if (c + 3 < NC) {
                uint32_t base = sbase + ((c + 3) & 3) * STAGEB;
                const __half* at = gA + (c + 3) * 32;
                const __half* wt = gW + (c + 3) * 32;
                #pragma unroll
                for (int k = 0; k < 4; k++)
                    cp_async16(base + fA + k * 64u * STB, at + (size_t)(k * 64) * K);
                #pragma unroll
                for (int k = 0; k < 2; k++)
                    cp_async16(base + A_BYTES + fA + k * 64u * STB, wt + (size_t)(k * 64) * K);
                CP_COMMIT();
            }

            const uint32_t stA = sbase + (c & 3) * STAGEB;
            const uint32_t stW = stA + A_BYTES;

            #pragma unroll
            for (int ks = 0; ks < 2; ks++) {
                const uint32_t kb = (uint32_t)(ks * 32);
                uint32_t a[4][4], b[4][4];
                #pragma unroll
                for (int mt = 0; mt < 4; mt++)
                    ldsm_x4(a[mt], stA + (uint32_t)(wm * 64 + mt * 16) * STB + kb + laneA);
                #pragma unroll
                for (int np = 0; np < 4; np++)
                    ldsm_x4(b[np], stW + (uint32_t)(wn * 64 + np * 16) * STB + kb + laneB);
                #pragma unroll
                for (int mt = 0; mt < 4; mt++)
                    #pragma unroll
                    for (int nt = 0; nt < 8; nt++)
                        mma_f16(acc[mt][nt], a[mt], &b[nt >> 1][(nt & 1) * 2]);
            }
        }

        // epilogue
        #pragma unroll
        for (int mt = 0; mt < 4; mt++) {
            #pragma unroll
            for (int nt = 0; nt < 8; nt++) {
                const int row0 = bm + wm * 64 + mt * 16 + (lane >> 2);
                const int col  = bn + wn * 64 + nt * 8 + (lane & 3) * 2;
                #pragma unroll
                for (int hh = 0; hh < 2; hh++) {
                    const int row = row0 + hh * 8;
                    float v0 = CLIP5(acc[mt][nt][hh * 2 + 0]);
                    float v1 = CLIP5(acc[mt][nt][hh * 2 + 1]);
                    if (MODE == 0) {
                        if (col < DI) {
                            *(__half2*)(out0h + (size_t)row * DI + col) =
                                __floats2half2_rn(v0, v1);
                        } else {
                            *(__half2*)(out1h + (size_t)row * DI + (col - DI)) =
                                __floats2half2_rn(tanhf(v0), tanhf(v1));
                        }
                    } else {
                        *(float2*)(out0f + (size_t)row * DM + col) = make_float2(v0, v1);
                    }
                }
            }
        }
    }
}

// ======================= SSM scan (round-7) =================================
__global__ __launch_bounds__(128) void scan_kernel(
    const float* __restrict__ A_log, const float* __restrict__ Bm,
    const float* __restrict__ Cm)
{
    int idx = blockIdx.x * blockDim.x + threadIdx.x;
    int b = idx / DI;
    int i = idx - b * DI;

    float decay[DS], bs[DS], cs[DS], hreg[DS];
    #pragma unroll
    for (int s = 0; s < DS; s++) {
        float a = A_log[i * DS + s];
        a = fminf(fmaxf(a, -5.0f), 0.0f);
        float Av = -__expf(a);
        Av = fminf(fmaxf(Av, -2.0f), -0.01f);
        decay[s] = Av * 0.9f;
        bs[s] = Bm[i * DS + s] * 0.1f;
        cs[s] = Cm[i * DS + s];
        hreg[s] = 0.f;
    }

    const __half* __restrict__ xin  = g_xh + (size_t)b * SEQ * DI + i;
    const __half* __restrict__ gin  = g_gh + (size_t)b * SEQ * DI + i;
    __half*       __restrict__ yout = g_y  + (size_t)b * SEQ * DI + i;

    #pragma unroll 8
    for (int t = 0; t < SEQ; t++) {
        float x  = __half2float(xin[(size_t)t * DI]);
        float gt = __half2float(gin[(size_t)t * DI]);
        float y = 0.f;
        #pragma unroll
        for (int s = 0; s < DS; s++) {
            float hs = fmaf(hreg[s], decay[s], x * bs[s]);
            hs = CLIP5(hs);
            hreg[s] = hs;
            y = fmaf(hs, cs[s], y);
        }
        y = CLIP5(y);
        yout[(size_t)t * DI] = __float2half_rn(y * gt);
    }
}

// ======================= streams (static init: before harness checkpoints) ==
struct HxStreams {
    cudaStream_t s2;
    cudaEvent_t ev[2];
    HxStreams() {
        cudaStreamCreateWithFlags(&s2, cudaStreamNonBlocking);
        for (int i = 0; i < 2; i++)
            cudaEventCreateWithFlags(&ev[i], cudaEventDisableTiming);
    }
};
static HxStreams g_hx;

// ======================= launch =============================================
extern "C" void kernel_launch(void* const* d_in, const int* in_sizes, int n_in,
                              void* d_out, int out_size)
{
    const float* x       = (const float*)d_in[0];
    const float* W_in    = (const float*)d_in[1];
    const float* W_out   = (const float*)d_in[2];
    const float* A_log   = (const float*)d_in[3];
    const float* Bm      = (const float*)d_in[4];
    const float* Cm      = (const float*)d_in[5];
    const float* ln_in_g = (const float*)d_in[6];
    const float* ln_in_b = (const float*)d_in[7];
    const float* ln_out_g= (const float*)d_in[8];
    const float* ln_out_b= (const float*)d_in[9];
    float* out = (float*)d_out;

    __half *p_xnorm, *p_xh, *p_gh, *p_y, *p_win, *p_wout;
    float *p_out1;
    int *p_ctr1, *p_ctr2;
    cudaGetSymbolAddress((void**)&p_xnorm, g_xnorm);
    cudaGetSymbolAddress((void**)&p_xh   , g_xh);
    cudaGetSymbolAddress((void**)&p_gh   , g_gh);
    cudaGetSymbolAddress((void**)&p_y    , g_y);
    cudaGetSymbolAddress((void**)&p_out1 , g_out1);
    cudaGetSymbolAddress((void**)&p_win  , g_win);
    cudaGetSymbolAddress((void**)&p_wout , g_wout);
    cudaGetSymbolAddress((void**)&p_ctr1 , g_ctr1);
    cudaGetSymbolAddress((void**)&p_ctr2 , g_ctr2);

    cudaFuncSetAttribute(mma_gemm_pers<0>, cudaFuncAttributeMaxDynamicSharedMemorySize, GEMM_SMEM);
    cudaFuncSetAttribute(mma_gemm_pers<1>, cudaFuncAttributeMaxDynamicSharedMemorySize, GEMM_SMEM);

    // 0) counters -> 0 (graph-replayable)
    cudaMemsetAsync(p_ctr1, 0, sizeof(int), 0);
    cudaMemsetAsync(p_ctr2, 0, sizeof(int), 0);

    // 0b) weights -> fp16 on fork stream, overlapped with LN_in
    cudaEventRecord(g_hx.ev[0], 0);
    cudaStreamWaitEvent(g_hx.s2, g_hx.ev[0], 0);
    {
        int total4 = (NDI2 * DM + DM * DI) / 4;
        prep_w<<<(total4 + 255) / 256, 256, 0, g_hx.s2>>>(W_in, W_out);
    }
    cudaEventRecord(g_hx.ev[1], g_hx.s2);

    // 1) input LN -> fp16 (default stream, concurrent with prep_w)
    ln_kernel<1><<<NTOK, 256>>>(x, ln_in_g, ln_in_b, p_xnorm);

    // join before GEMM1
    cudaStreamWaitEvent(0, g_hx.ev[1], 0);

    // 2) GEMM1: [8192 x 3072] = LN(x) @ W_in^T, clip/split/tanh -> fp16
    mma_gemm_pers<0><<<NPERS, 256, GEMM_SMEM>>>(
        p_xnorm, p_win, DM, NDI2 / BN, (NTOK / BM) * (NDI2 / BN), p_ctr1,
        p_xh, p_gh, nullptr);

    // 3) scan: fp16(y*tanh(gate)) -> g_y
    scan_kernel<<<(NB * DI) / 128, 128>>>(A_log, Bm, Cm);

    // 4) GEMM2: [8192 x 1024] = y @ W_out^T, clip -> fp32
    mma_gemm_pers<1><<<NPERS, 256, GEMM_SMEM>>>(
        p_y, p_wout, DI, DM / BN, (NTOK / BM) * (DM / BN), p_ctr2,
        nullptr, nullptr, p_out1);

    // 5) output LN -> fp32 d_out
    ln_kernel<0><<<NTOK, 256>>>(p_out1, ln_out_g, ln_out_b, out);
}

// round 12
// speedup vs baseline: 1.5418x; 1.0680x over previous
#include <cuda_runtime.h>
#include <cuda_fp16.h>
#include <cstdint>

// ---------------------------------------------------------------------------
// SimplifiedMamba2Block on GB300 (sm_103a), compute_103-safe.
// Round 12: discriminate "HMMA issue ceiling" vs "2-warps/SMSP stall-bound":
//   - GEMM: BM=128 tiles, 2 CTAs/SM co-resident -> 4 warps/SMSP (2x latency
//     hiding), same BK=32 / ldmatrix / 4-stage cp.async ring as R7.
//   - no-op 3rd launch so ncu's capture (4th kernel) lands on mma_gemm<0>.
//   - prep_w overlapped with LN_in on fork stream (from R11).
// ---------------------------------------------------------------------------

#define NTOK   8192
#define DM     1024
#define DI     1536
#define DS     8
#define NDI2   3072
#define SEQ    2048
#define NB     4

#define CLIP5(v) fminf(fmaxf((v), -5.0f), 5.0f)

// scratch (__device__ globals per allocation-free rule)
__device__ __half g_xnorm[NTOK * DM];    // LN(x), fp16
__device__ __half g_xh   [NTOK * DI];    // GEMM1 out ssm half, fp16
__device__ __half g_gh   [NTOK * DI];    // GEMM1 out tanh gate, fp16
__device__ __half g_y    [NTOK * DI];    // scan out y*gate, fp16 (GEMM2 A)
__device__ float  g_out1 [NTOK * DM];    // GEMM2 out, fp32
__device__ __half g_win  [NDI2 * DM];    // fp16 W_in
__device__ __half g_wout [DM * DI];      // fp16 W_out

// ======================= helpers ===========================================
__device__ __forceinline__ uint32_t smem_u32(const void* p) {
    uint32_t r;
    asm("{ .reg .u64 t; cvta.to.shared.u64 t, %1; cvt.u32.u64 %0, t; }"
        : "=r"(r) : "l"(p));
    return r;
}
__device__ __forceinline__ void cp_async16(uint32_t saddr, const void* gaddr) {
    asm volatile("cp.async.cg.shared.global [%0], [%1], 16;"
                 :: "r"(saddr), "l"(gaddr) : "memory");
}
#define CP_COMMIT() asm volatile("cp.async.commit_group;" ::: "memory")
#define CP_WAIT(n)  asm volatile("cp.async.wait_group %0;" :: "n"(n) : "memory")

__device__ __forceinline__ void mma_f16(float* d, const uint32_t* a, const uint32_t* b) {
    asm volatile(
        "mma.sync.aligned.m16n8k16.row.col.f32.f16.f16.f32 "
        "{%0,%1,%2,%3}, {%4,%5,%6,%7}, {%8,%9}, {%0,%1,%2,%3};"
        : "+f"(d[0]), "+f"(d[1]), "+f"(d[2]), "+f"(d[3])
        : "r"(a[0]), "r"(a[1]), "r"(a[2]), "r"(a[3]), "r"(b[0]), "r"(b[1]));
}
__device__ __forceinline__ void ldsm_x4(uint32_t* r, uint32_t addr) {
    asm volatile("ldmatrix.sync.aligned.m8n8.x4.shared.b16 {%0,%1,%2,%3}, [%4];"
                 : "=r"(r[0]), "=r"(r[1]), "=r"(r[2]), "=r"(r[3]) : "r"(addr));
}

// ======================= weight prep (fp32 -> fp16) =========================
__global__ __launch_bounds__(256) void prep_w(
    const float* __restrict__ win, const float* __restrict__ wout)
{
    const int n1 = (NDI2 * DM) / 4;
    const int n2 = (DM * DI) / 4;
    int i = blockIdx.x * blockDim.x + threadIdx.x;
    if (i < n1) {
        float4 v = ((const float4*)win)[i];
        __half2 h0 = __floats2half2_rn(v.x, v.y);
        __half2 h1 = __floats2half2_rn(v.z, v.w);
        uint2 u; u.x = *(uint32_t*)&h0; u.y = *(uint32_t*)&h1;
        ((uint2*)g_win)[i] = u;
    } else if (i < n1 + n2) {
        float4 v = ((const float4*)wout)[i - n1];
        __half2 h0 = __floats2half2_rn(v.x, v.y);
        __half2 h1 = __floats2half2_rn(v.z, v.w);
        uint2 u; u.x = *(uint32_t*)&h0; u.y = *(uint32_t*)&h1;
        ((uint2*)g_wout)[i - n1] = u;
    }
}

// ======================= no-op (shifts ncu capture onto GEMM1) ==============
__global__ void nop_kernel() {}

// ======================= LayerNorm =========================================
template<int HALF_OUT>
__global__ __launch_bounds__(256) void ln_kernel(
    const float* __restrict__ in, const float* __restrict__ g,
    const float* __restrict__ b, void* __restrict__ outv)
{
    __shared__ float s_sum[8], s_sq[8];
    int row = blockIdx.x;
    int tid = threadIdx.x;
    const float4 v = *(const float4*)(in + (size_t)row * DM + tid * 4);

    float sum = v.x + v.y + v.z + v.w;
    float sq  = v.x*v.x + v.y*v.y + v.z*v.z + v.w*v.w;
    #pragma unroll
    for (int o = 16; o > 0; o >>= 1) {
        sum += __shfl_xor_sync(0xffffffffu, sum, o);
        sq  += __shfl_xor_sync(0xffffffffu, sq , o);
    }
    int wid = tid >> 5, lid = tid & 31;
    if (lid == 0) { s_sum[wid] = sum; s_sq[wid] = sq; }
    __syncthreads();
    if (wid == 0) {
        float a = (lid < 8) ? s_sum[lid] : 0.f;
        float c = (lid < 8) ? s_sq [lid] : 0.f;
        #pragma unroll
        for (int o = 4; o > 0; o >>= 1) {
            a += __shfl_xor_sync(0xffffffffu, a, o);
            c += __shfl_xor_sync(0xffffffffu, c, o);
        }
        if (lid == 0) { s_sum[0] = a; s_sq[0] = c; }
    }
    __syncthreads();
    float mean = s_sum[0] * (1.0f / DM);
    float var  = s_sq[0] * (1.0f / DM) - mean * mean;
    float rstd = rsqrtf(var + 1e-5f);

    const float4 gv = *(const float4*)(g + tid * 4);
    const float4 bv = *(const float4*)(b + tid * 4);
    float4 o4;
    o4.x = (v.x - mean) * rstd * gv.x + bv.x;
    o4.y = (v.y - mean) * rstd * gv.y + bv.y;
    o4.z = (v.z - mean) * rstd * gv.z + bv.z;
    o4.w = (v.w - mean) * rstd * gv.w + bv.w;
    if (HALF_OUT) {
        __half2 h0 = __floats2half2_rn(o4.x, o4.y);
        __half2 h1 = __floats2half2_rn(o4.z, o4.w);
        uint2 u; u.x = *(uint32_t*)&h0; u.y = *(uint32_t*)&h1;
        *(uint2*)((__half*)outv + (size_t)row * DM + tid * 4) = u;
    } else {
        *(float4*)((float*)outv + (size_t)row * DM + tid * 4) = o4;
    }
}

// ======================= mma.sync f16 GEMM (128x128 tile, 2 CTA/SM) =========
// C = A @ W^T. A: MxK rm fp16, W: NxK rm fp16, K % 32 == 0, NC >= 3.
// 256 threads = 8 warps in 4(m) x 2(n); warp tile 32x64 -> acc[2][8][4] (64
// regs). BK=32; 4-stage cp.async ring (20480 B/stage, 81920/CTA -> two CTAs
// co-reside per SM = 4 warps/SMSP). Fragments via ldmatrix.x4; smem row
// stride 40 halves (80B).
// MODE 0: clip; col<DI -> fp16 out0h (x_ssm); else tanh -> fp16 out1h (gate)
// MODE 1: clip -> fp32 out0f
// ---------------------------------------------------------------------------
#define BM      128
#define BN      128
#define STB     80u
#define A_BYTES (BM * STB)          // 10240
#define W_BYTES (BN * STB)          // 10240
#define STAGEB  (A_BYTES + W_BYTES) // 20480
#define NSTAGE  4
#define GEMM_SMEM (NSTAGE * STAGEB) // 81920

template<int MODE>
__global__ __launch_bounds__(256, 2) void mma_gemm(
    const __half* __restrict__ A, const __half* __restrict__ W, int K,
    __half* __restrict__ out0h, __half* __restrict__ out1h,
    float* __restrict__ out0f)
{
    extern __shared__ __align__(16) char dynsmem[];

    const int tid  = threadIdx.x;
    const int lane = tid & 31;
    const int wid  = tid >> 5;
    const int wm   = wid & 3;          // warp m index (0..3) -> 32 rows
    const int wn   = wid >> 2;         // warp n index (0..1) -> 64 cols
    const int bm   = blockIdx.y * BM;
    const int bn   = blockIdx.x * BN;

    float acc[2][8][4];
    #pragma unroll
    for (int mt = 0; mt < 2; mt++)
        #pragma unroll
        for (int nt = 0; nt < 8; nt++)
            #pragma unroll
            for (int f = 0; f < 4; f++) acc[mt][nt][f] = 0.f;

    // ---- fill addressing: 1024 x 16B ops/stage, 4 per thread ----
    const int frow = tid >> 2;         // 0..63
    const int fseg = tid & 3;
    const uint32_t sbase = smem_u32(dynsmem);
    const uint32_t fA = (uint32_t)frow * STB + (uint32_t)fseg * 16u;
    const __half* gA = A + (size_t)(bm + frow) * K + fseg * 8;
    const __half* gW = W + (size_t)(bn + frow) * K + fseg * 8;

    const int NC = K / 32;

    // ---- per-lane ldmatrix offsets (same frag layouts as R7) ----
    const uint32_t laneA = (uint32_t)(lane & 15) * STB + (uint32_t)(lane >> 4) * 16u;
    const uint32_t laneB = (uint32_t)(((lane >> 4) << 3) + (lane & 7)) * STB
                         + (uint32_t)((lane >> 3) & 1) * 16u;

    // ---- prologue: stages 0..2 ----
    #pragma unroll
    for (int t = 0; t < 3; t++) {
        uint32_t base = sbase + t * STAGEB;
        const __half* at = gA + t * 32;
        const __half* wt = gW + t * 32;
        #pragma unroll
        for (int k = 0; k < 2; k++)
            cp_async16(base + fA + k * 64u * STB, at + (size_t)(k * 64) * K);
        #pragma unroll
        for (int k = 0; k < 2; k++)
            cp_async16(base + A_BYTES + fA + k * 64u * STB, wt + (size_t)(k * 64) * K);
        CP_COMMIT();
    }

    for (int c = 0; c < NC; c++) {
        if (c + 3 <= NC)      { CP_WAIT(2); }
        else if (c + 2 == NC) { CP_WAIT(1); }
        else                  { CP_WAIT(0); }
        __syncthreads();

        if (c + 3 < NC) {              // prefetch tile c+3
            uint32_t base = sbase + ((c + 3) & 3) * STAGEB;
            const __half* at = gA + (c + 3) * 32;
            const __half* wt = gW + (c + 3) * 32;
            #pragma unroll
            for (int k = 0; k < 2; k++)
                cp_async16(base + fA + k * 64u * STB, at + (size_t)(k * 64) * K);
            #pragma unroll
            for (int k = 0; k < 2; k++)
                cp_async16(base + A_BYTES + fA + k * 64u * STB, wt + (size_t)(k * 64) * K);
            CP_COMMIT();
        }

        const uint32_t stA = sbase + (c & 3) * STAGEB;
        const uint32_t stW = stA + A_BYTES;

        #pragma unroll
        for (int ks = 0; ks < 2; ks++) {
            const uint32_t kb = (uint32_t)(ks * 32);
            uint32_t a[2][4], b[4][4];
            #pragma unroll
            for (int mt = 0; mt < 2; mt++)
                ldsm_x4(a[mt], stA + (uint32_t)(wm * 32 + mt * 16) * STB + kb + laneA);
            #pragma unroll
            for (int np = 0; np < 4; np++)
                ldsm_x4(b[np], stW + (uint32_t)(wn * 64 + np * 16) * STB + kb + laneB);
            #pragma unroll
            for (int mt = 0; mt < 2; mt++)
                #pragma unroll
                for (int nt = 0; nt < 8; nt++)
                    mma_f16(acc[mt][nt], a[mt], &b[nt >> 1][(nt & 1) * 2]);
        }
    }

    // ---- epilogue ----
    #pragma unroll
    for (int mt = 0; mt < 2; mt++) {
        #pragma unroll
        for (int nt = 0; nt < 8; nt++) {
            const int row0 = bm + wm * 32 + mt * 16 + (lane >> 2);
            const int col  = bn + wn * 64 + nt * 8 + (lane & 3) * 2;
            #pragma unroll
            for (int hh = 0; hh < 2; hh++) {
                const int row = row0 + hh * 8;
                float v0 = CLIP5(acc[mt][nt][hh * 2 + 0]);
                float v1 = CLIP5(acc[mt][nt][hh * 2 + 1]);
                if (MODE == 0) {
                    if (col < DI) {
                        *(__half2*)(out0h + (size_t)row * DI + col) =
                            __floats2half2_rn(v0, v1);
                    } else {
                        *(__half2*)(out1h + (size_t)row * DI + (col - DI)) =
                            __floats2half2_rn(tanhf(v0), tanhf(v1));
                    }
                } else {
                    *(float2*)(out0f + (size_t)row * DM + col) = make_float2(v0, v1);
                }
            }
        }
    }
}

// ======================= SSM scan (round-7) =================================
__global__ __launch_bounds__(128) void scan_kernel(
    const float* __restrict__ A_log, const float* __restrict__ Bm,
    const float* __restrict__ Cm)
{
    int idx = blockIdx.x * blockDim.x + threadIdx.x;
    int b = idx / DI;
    int i = idx - b * DI;

    float decay[DS], bs[DS], cs[DS], hreg[DS];
    #pragma unroll
    for (int s = 0; s < DS; s++) {
        float a = A_log[i * DS + s];
        a = fminf(fmaxf(a, -5.0f), 0.0f);
        float Av = -__expf(a);
        Av = fminf(fmaxf(Av, -2.0f), -0.01f);
        decay[s] = Av * 0.9f;
        bs[s] = Bm[i * DS + s] * 0.1f;
        cs[s] = Cm[i * DS + s];
        hreg[s] = 0.f;
    }

    const __half* __restrict__ xin  = g_xh + (size_t)b * SEQ * DI + i;
    const __half* __restrict__ gin  = g_gh + (size_t)b * SEQ * DI + i;
    __half*       __restrict__ yout = g_y  + (size_t)b * SEQ * DI + i;

    #pragma unroll 8
    for (int t = 0; t < SEQ; t++) {
        float x  = __half2float(xin[(size_t)t * DI]);
        float gt = __half2float(gin[(size_t)t * DI]);
        float y = 0.f;
        #pragma unroll
        for (int s = 0; s < DS; s++) {
            float hs = fmaf(hreg[s], decay[s], x * bs[s]);
            hs = CLIP5(hs);
            hreg[s] = hs;
            y = fmaf(hs, cs[s], y);
        }
        y = CLIP5(y);
        yout[(size_t)t * DI] = __float2half_rn(y * gt);
    }
}

// ======================= streams (static init: before harness checkpoints) ==
struct HxStreams {
    cudaStream_t s2;
    cudaEvent_t ev[2];
    HxStreams() {
        cudaStreamCreateWithFlags(&s2, cudaStreamNonBlocking);
        for (int i = 0; i < 2; i++)
            cudaEventCreateWithFlags(&ev[i], cudaEventDisableTiming);
    }
};
static HxStreams g_hx;

// ======================= launch =============================================
extern "C" void kernel_launch(void* const* d_in, const int* in_sizes, int n_in,
                              void* d_out, int out_size)
{
    const float* x       = (const float*)d_in[0];
    const float* W_in    = (const float*)d_in[1];
    const float* W_out   = (const float*)d_in[2];
    const float* A_log   = (const float*)d_in[3];
    const float* Bm      = (const float*)d_in[4];
    const float* Cm      = (const float*)d_in[5];
    const float* ln_in_g = (const float*)d_in[6];
    const float* ln_in_b = (const float*)d_in[7];
    const float* ln_out_g= (const float*)d_in[8];
    const float* ln_out_b= (const float*)d_in[9];
    float* out = (float*)d_out;

    __half *p_xnorm, *p_xh, *p_gh, *p_y, *p_win, *p_wout;
    float *p_out1;
    cudaGetSymbolAddress((void**)&p_xnorm, g_xnorm);
    cudaGetSymbolAddress((void**)&p_xh   , g_xh);
    cudaGetSymbolAddress((void**)&p_gh   , g_gh);
    cudaGetSymbolAddress((void**)&p_y    , g_y);
    cudaGetSymbolAddress((void**)&p_out1 , g_out1);
    cudaGetSymbolAddress((void**)&p_win  , g_win);
    cudaGetSymbolAddress((void**)&p_wout , g_wout);

    cudaFuncSetAttribute(mma_gemm<0>, cudaFuncAttributeMaxDynamicSharedMemorySize, GEMM_SMEM);
    cudaFuncSetAttribute(mma_gemm<1>, cudaFuncAttributeMaxDynamicSharedMemorySize, GEMM_SMEM);

    // launch #1: weights -> fp16 on fork stream, overlapped with LN_in
    cudaEventRecord(g_hx.ev[0], 0);
    cudaStreamWaitEvent(g_hx.s2, g_hx.ev[0], 0);
    {
        int total4 = (NDI2 * DM + DM * DI) / 4;
        prep_w<<<(total4 + 255) / 256, 256, 0, g_hx.s2>>>(W_in, W_out);
    }
    cudaEventRecord(g_hx.ev[1], g_hx.s2);

    // launch #2: input LN -> fp16 (concurrent with prep_w)
    ln_kernel<1><<<NTOK, 256>>>(x, ln_in_g, ln_in_b, p_xnorm);

    // launch #3: no-op, so ncu's capture (4th kernel) lands on GEMM1
    nop_kernel<<<1, 32>>>();

    // join before GEMM1
    cudaStreamWaitEvent(0, g_hx.ev[1], 0);

    // launch #4: GEMM1: [8192 x 3072] = LN(x) @ W_in^T, clip/split/tanh
    {
        dim3 grid(NDI2 / BN, NTOK / BM);   // (24, 64) = 1536 CTAs
        mma_gemm<0><<<grid, 256, GEMM_SMEM>>>(p_xnorm, p_win, DM, p_xh, p_gh, nullptr);
    }

    // launch #5: scan: fp16(y*tanh(gate)) -> g_y
    scan_kernel<<<(NB * DI) / 128, 128>>>(A_log, Bm, Cm);

    // launch #6: GEMM2: [8192 x 1024] = y @ W_out^T, clip -> fp32
    {
        dim3 grid(DM / BN, NTOK / BM);     // (8, 64) = 512 CTAs
        mma_gemm<1><<<grid, 256, GEMM_SMEM>>>(p_y, p_wout, DI, nullptr, nullptr, p_out1);
    }

    // launch #7: output LN -> fp32 d_out
    ln_kernel<0><<<NTOK, 256>>>(p_out1, ln_out_g, ln_out_b, out);
}

// round 13
// speedup vs baseline: 3.8985x; 2.5285x over previous
#include <cuda_runtime.h>
#include <cuda_fp16.h>
#include <cstdint>

// ---------------------------------------------------------------------------
// SimplifiedMamba2Block on GB300 (sm_103a), compute_103-safe.
// Round 13: R12 GEMMs (tensor pipe confirmed: 47.8% util, G1=177us) +
// CHUNKED PARALLEL SCAN: decay in [-0.9,-0.009] and clip is 1-Lipschitz =>
// perturbations decay <=0.9^t, so chunks restarted from h=0 with 128 warm-up
// steps are exact to ~7e-6. 8 chunks/sequence -> 49152 threads (x8 latency
// hiding) at 1.44x work.
// ---------------------------------------------------------------------------

#define NTOK   8192
#define DM     1024
#define DI     1536
#define DS     8
#define NDI2   3072
#define SEQ    2048
#define NB     4

#define CHUNK  256
#define WARM   128
#define NCHUNK (SEQ / CHUNK)     // 8

#define CLIP5(v) fminf(fmaxf((v), -5.0f), 5.0f)

// scratch (__device__ globals per allocation-free rule)
__device__ __half g_xnorm[NTOK * DM];    // LN(x), fp16
__device__ __half g_xh   [NTOK * DI];    // GEMM1 out ssm half, fp16
__device__ __half g_gh   [NTOK * DI];    // GEMM1 out tanh gate, fp16
__device__ __half g_y    [NTOK * DI];    // scan out y*gate, fp16 (GEMM2 A)
__device__ float  g_out1 [NTOK * DM];    // GEMM2 out, fp32
__device__ __half g_win  [NDI2 * DM];    // fp16 W_in
__device__ __half g_wout [DM * DI];      // fp16 W_out

// ======================= helpers ===========================================
__device__ __forceinline__ uint32_t smem_u32(const void* p) {
    uint32_t r;
    asm("{ .reg .u64 t; cvta.to.shared.u64 t, %1; cvt.u32.u64 %0, t; }"
        : "=r"(r) : "l"(p));
    return r;
}
__device__ __forceinline__ void cp_async16(uint32_t saddr, const void* gaddr) {
    asm volatile("cp.async.cg.shared.global [%0], [%1], 16;"
                 :: "r"(saddr), "l"(gaddr) : "memory");
}
#define CP_COMMIT() asm volatile("cp.async.commit_group;" ::: "memory")
#define CP_WAIT(n)  asm volatile("cp.async.wait_group %0;" :: "n"(n) : "memory")

__device__ __forceinline__ void mma_f16(float* d, const uint32_t* a, const uint32_t* b) {
    asm volatile(
        "mma.sync.aligned.m16n8k16.row.col.f32.f16.f16.f32 "
        "{%0,%1,%2,%3}, {%4,%5,%6,%7}, {%8,%9}, {%0,%1,%2,%3};"
        : "+f"(d[0]), "+f"(d[1]), "+f"(d[2]), "+f"(d[3])
        : "r"(a[0]), "r"(a[1]), "r"(a[2]), "r"(a[3]), "r"(b[0]), "r"(b[1]));
}
__device__ __forceinline__ void ldsm_x4(uint32_t* r, uint32_t addr) {
    asm volatile("ldmatrix.sync.aligned.m8n8.x4.shared.b16 {%0,%1,%2,%3}, [%4];"
                 : "=r"(r[0]), "=r"(r[1]), "=r"(r[2]), "=r"(r[3]) : "r"(addr));
}

// ======================= weight prep (fp32 -> fp16) =========================
__global__ __launch_bounds__(256) void prep_w(
    const float* __restrict__ win, const float* __restrict__ wout)
{
    const int n1 = (NDI2 * DM) / 4;
    const int n2 = (DM * DI) / 4;
    int i = blockIdx.x * blockDim.x + threadIdx.x;
    if (i < n1) {
        float4 v = ((const float4*)win)[i];
        __half2 h0 = __floats2half2_rn(v.x, v.y);
        __half2 h1 = __floats2half2_rn(v.z, v.w);
        uint2 u; u.x = *(uint32_t*)&h0; u.y = *(uint32_t*)&h1;
        ((uint2*)g_win)[i] = u;
    } else if (i < n1 + n2) {
        float4 v = ((const float4*)wout)[i - n1];
        __half2 h0 = __floats2half2_rn(v.x, v.y);
        __half2 h1 = __floats2half2_rn(v.z, v.w);
        uint2 u; u.x = *(uint32_t*)&h0; u.y = *(uint32_t*)&h1;
        ((uint2*)g_wout)[i - n1] = u;
    }
}

// ======================= LayerNorm =========================================
template<int HALF_OUT>
__global__ __launch_bounds__(256) void ln_kernel(
    const float* __restrict__ in, const float* __restrict__ g,
    const float* __restrict__ b, void* __restrict__ outv)
{
    __shared__ float s_sum[8], s_sq[8];
    int row = blockIdx.x;
    int tid = threadIdx.x;
    const float4 v = *(const float4*)(in + (size_t)row * DM + tid * 4);

    float sum = v.x + v.y + v.z + v.w;
    float sq  = v.x*v.x + v.y*v.y + v.z*v.z + v.w*v.w;
    #pragma unroll
    for (int o = 16; o > 0; o >>= 1) {
        sum += __shfl_xor_sync(0xffffffffu, sum, o);
        sq  += __shfl_xor_sync(0xffffffffu, sq , o);
    }
    int wid = tid >> 5, lid = tid & 31;
    if (lid == 0) { s_sum[wid] = sum; s_sq[wid] = sq; }
    __syncthreads();
    if (wid == 0) {
        float a = (lid < 8) ? s_sum[lid] : 0.f;
        float c = (lid < 8) ? s_sq [lid] : 0.f;
        #pragma unroll
        for (int o = 4; o > 0; o >>= 1) {
            a += __shfl_xor_sync(0xffffffffu, a, o);
            c += __shfl_xor_sync(0xffffffffu, c, o);
        }
        if (lid == 0) { s_sum[0] = a; s_sq[0] = c; }
    }
    __syncthreads();
    float mean = s_sum[0] * (1.0f / DM);
    float var  = s_sq[0] * (1.0f / DM) - mean * mean;
    float rstd = rsqrtf(var + 1e-5f);

    const float4 gv = *(const float4*)(g + tid * 4);
    const float4 bv = *(const float4*)(b + tid * 4);
    float4 o4;
    o4.x = (v.x - mean) * rstd * gv.x + bv.x;
    o4.y = (v.y - mean) * rstd * gv.y + bv.y;
    o4.z = (v.z - mean) * rstd * gv.z + bv.z;
    o4.w = (v.w - mean) * rstd * gv.w + bv.w;
    if (HALF_OUT) {
        __half2 h0 = __floats2half2_rn(o4.x, o4.y);
        __half2 h1 = __floats2half2_rn(o4.z, o4.w);
        uint2 u; u.x = *(uint32_t*)&h0; u.y = *(uint32_t*)&h1;
        *(uint2*)((__half*)outv + (size_t)row * DM + tid * 4) = u;
    } else {
        *(float4*)((float*)outv + (size_t)row * DM + tid * 4) = o4;
    }
}

// ======================= mma.sync f16 GEMM (128x128 tile, 2 CTA/SM) =========
// Unchanged from R12 (G1 measured 177us, tensor pipe 47.8%).
// ---------------------------------------------------------------------------
#define BM      128
#define BN      128
#define STB     80u
#define A_BYTES (BM * STB)          // 10240
#define W_BYTES (BN * STB)          // 10240
#define STAGEB  (A_BYTES + W_BYTES) // 20480
#define NSTAGE  4
#define GEMM_SMEM (NSTAGE * STAGEB) // 81920

template<int MODE>
__global__ __launch_bounds__(256, 2) void mma_gemm(
    const __half* __restrict__ A, const __half* __restrict__ W, int K,
    __half* __restrict__ out0h, __half* __restrict__ out1h,
    float* __restrict__ out0f)
{
    extern __shared__ __align__(16) char dynsmem[];

    const int tid  = threadIdx.x;
    const int lane = tid & 31;
    const int wid  = tid >> 5;
    const int wm   = wid & 3;
    const int wn   = wid >> 2;
    const int bm   = blockIdx.y * BM;
    const int bn   = blockIdx.x * BN;

    float acc[2][8][4];
    #pragma unroll
    for (int mt = 0; mt < 2; mt++)
        #pragma unroll
        for (int nt = 0; nt < 8; nt++)
            #pragma unroll
            for (int f = 0; f < 4; f++) acc[mt][nt][f] = 0.f;

    const int frow = tid >> 2;
    const int fseg = tid & 3;
    const uint32_t sbase = smem_u32(dynsmem);
    const uint32_t fA = (uint32_t)frow * STB + (uint32_t)fseg * 16u;
    const __half* gA = A + (size_t)(bm + frow) * K + fseg * 8;
    const __half* gW = W + (size_t)(bn + frow) * K + fseg * 8;

    const int NC = K / 32;

    const uint32_t laneA = (uint32_t)(lane & 15) * STB + (uint32_t)(lane >> 4) * 16u;
    const uint32_t laneB = (uint32_t)(((lane >> 4) << 3) + (lane & 7)) * STB
                         + (uint32_t)((lane >> 3) & 1) * 16u;

    #pragma unroll
    for (int t = 0; t < 3; t++) {
        uint32_t base = sbase + t * STAGEB;
        const __half* at = gA + t * 32;
        const __half* wt = gW + t * 32;
        #pragma unroll
        for (int k = 0; k < 2; k++)
            cp_async16(base + fA + k * 64u * STB, at + (size_t)(k * 64) * K);
        #pragma unroll
        for (int k = 0; k < 2; k++)
            cp_async16(base + A_BYTES + fA + k * 64u * STB, wt + (size_t)(k * 64) * K);
        CP_COMMIT();
    }

    for (int c = 0; c < NC; c++) {
        if (c + 3 <= NC)      { CP_WAIT(2); }
        else if (c + 2 == NC) { CP_WAIT(1); }
        else                  { CP_WAIT(0); }
        __syncthreads();

        if (c + 3 < NC) {
            uint32_t base = sbase + ((c + 3) & 3) * STAGEB;
            const __half* at = gA + (c + 3) * 32;
            const __half* wt = gW + (c + 3) * 32;
            #pragma unroll
            for (int k = 0; k < 2; k++)
                cp_async16(base + fA + k * 64u * STB, at + (size_t)(k * 64) * K);
            #pragma unroll
            for (int k = 0; k < 2; k++)
                cp_async16(base + A_BYTES + fA + k * 64u * STB, wt + (size_t)(k * 64) * K);
            CP_COMMIT();
        }

        const uint32_t stA = sbase + (c & 3) * STAGEB;
        const uint32_t stW = stA + A_BYTES;

        #pragma unroll
        for (int ks = 0; ks < 2; ks++) {
            const uint32_t kb = (uint32_t)(ks * 32);
            uint32_t a[2][4], b[4][4];
            #pragma unroll
            for (int mt = 0; mt < 2; mt++)
                ldsm_x4(a[mt], stA + (uint32_t)(wm * 32 + mt * 16) * STB + kb + laneA);
            #pragma unroll
            for (int np = 0; np < 4; np++)
                ldsm_x4(b[np], stW + (uint32_t)(wn * 64 + np * 16) * STB + kb + laneB);
            #pragma unroll
            for (int mt = 0; mt < 2; mt++)
                #pragma unroll
                for (int nt = 0; nt < 8; nt++)
                    mma_f16(acc[mt][nt], a[mt], &b[nt >> 1][(nt & 1) * 2]);
        }
    }

    #pragma unroll
    for (int mt = 0; mt < 2; mt++) {
        #pragma unroll
        for (int nt = 0; nt < 8; nt++) {
            const int row0 = bm + wm * 32 + mt * 16 + (lane >> 2);
            const int col  = bn + wn * 64 + nt * 8 + (lane & 3) * 2;
            #pragma unroll
            for (int hh = 0; hh < 2; hh++) {
                const int row = row0 + hh * 8;
                float v0 = CLIP5(acc[mt][nt][hh * 2 + 0]);
                float v1 = CLIP5(acc[mt][nt][hh * 2 + 1]);
                if (MODE == 0) {
                    if (col < DI) {
                        *(__half2*)(out0h + (size_t)row * DI + col) =
                            __floats2half2_rn(v0, v1);
                    } else {
                        *(__half2*)(out1h + (size_t)row * DI + (col - DI)) =
                            __floats2half2_rn(tanhf(v0), tanhf(v1));
                    }
                } else {
                    *(float2*)(out0f + (size_t)row * DM + col) = make_float2(v0, v1);
                }
            }
        }
    }
}

// ======================= chunked SSM scan ===================================
// decay in [-0.9,-0.009]; clip is 1-Lipschitz => state perturbations decay
// <= 0.9^t. Each (b, channel, chunk) thread restarts h=0 at t0-WARM, runs
// WARM discarded steps (error <= 5*0.9^128 ~ 7e-6), then emits CHUNK outputs.
// 49152 threads (8x parallelism), consecutive threads -> consecutive i.
// ---------------------------------------------------------------------------
__global__ __launch_bounds__(128) void scan_kernel(
    const float* __restrict__ A_log, const float* __restrict__ Bm,
    const float* __restrict__ Cm)
{
    const int idx = blockIdx.x * blockDim.x + threadIdx.x; // 0..49151
    const int i   = idx % DI;
    const int bc  = idx / DI;          // 0..31
    const int b   = bc >> 3;           // batch
    const int c   = bc & 7;            // chunk

    float decay[DS], bs[DS], cs[DS], hreg[DS];
    #pragma unroll
    for (int s = 0; s < DS; s++) {
        float a = A_log[i * DS + s];
        a = fminf(fmaxf(a, -5.0f), 0.0f);
        float Av = -__expf(a);
        Av = fminf(fmaxf(Av, -2.0f), -0.01f);
        decay[s] = Av * 0.9f;
        bs[s] = Bm[i * DS + s] * 0.1f;
        cs[s] = Cm[i * DS + s];
        hreg[s] = 0.f;
    }

    const __half* __restrict__ xin  = g_xh + (size_t)b * SEQ * DI + i;
    const __half* __restrict__ gin  = g_gh + (size_t)b * SEQ * DI + i;
    __half*       __restrict__ yout = g_y  + (size_t)b * SEQ * DI + i;

    const int t0 = c * CHUNK;
    const int ts = (c == 0) ? 0 : (t0 - WARM);

    // warm-up: converge h, discard outputs (no gate loads, no y, no store)
    #pragma unroll 4
    for (int t = ts; t < t0; t++) {
        float x = __half2float(xin[(size_t)t * DI]);
        #pragma unroll
        for (int s = 0; s < DS; s++) {
            float hs = fmaf(hreg[s], decay[s], x * bs[s]);
            hreg[s] = CLIP5(hs);
        }
    }

    // emit chunk
    #pragma unroll 4
    for (int t = t0; t < t0 + CHUNK; t++) {
        float x  = __half2float(xin[(size_t)t * DI]);
        float gt = __half2float(gin[(size_t)t * DI]);
        float y = 0.f;
        #pragma unroll
        for (int s = 0; s < DS; s++) {
            float hs = fmaf(hreg[s], decay[s], x * bs[s]);
            hs = CLIP5(hs);
            hreg[s] = hs;
            y = fmaf(hs, cs[s], y);
        }
        y = CLIP5(y);
        yout[(size_t)t * DI] = __float2half_rn(y * gt);
    }
}

// ======================= streams (static init: before harness checkpoints) ==
struct HxStreams {
    cudaStream_t s2;
    cudaEvent_t ev[2];
    HxStreams() {
        cudaStreamCreateWithFlags(&s2, cudaStreamNonBlocking);
        for (int i = 0; i < 2; i++)
            cudaEventCreateWithFlags(&ev[i], cudaEventDisableTiming);
    }
};
static HxStreams g_hx;

// ======================= launch =============================================
extern "C" void kernel_launch(void* const* d_in, const int* in_sizes, int n_in,
                              void* d_out, int out_size)
{
    const float* x       = (const float*)d_in[0];
    const float* W_in    = (const float*)d_in[1];
    const float* W_out   = (const float*)d_in[2];
    const float* A_log   = (const float*)d_in[3];
    const float* Bm      = (const float*)d_in[4];
    const float* Cm      = (const float*)d_in[5];
    const float* ln_in_g = (const float*)d_in[6];
    const float* ln_in_b = (const float*)d_in[7];
    const float* ln_out_g= (const float*)d_in[8];
    const float* ln_out_b= (const float*)d_in[9];
    float* out = (float*)d_out;

    __half *p_xnorm, *p_xh, *p_gh, *p_y, *p_win, *p_wout;
    float *p_out1;
    cudaGetSymbolAddress((void**)&p_xnorm, g_xnorm);
    cudaGetSymbolAddress((void**)&p_xh   , g_xh);
    cudaGetSymbolAddress((void**)&p_gh   , g_gh);
    cudaGetSymbolAddress((void**)&p_y    , g_y);
    cudaGetSymbolAddress((void**)&p_out1 , g_out1);
    cudaGetSymbolAddress((void**)&p_win  , g_win);
    cudaGetSymbolAddress((void**)&p_wout , g_wout);

    cudaFuncSetAttribute(mma_gemm<0>, cudaFuncAttributeMaxDynamicSharedMemorySize, GEMM_SMEM);
    cudaFuncSetAttribute(mma_gemm<1>, cudaFuncAttributeMaxDynamicSharedMemorySize, GEMM_SMEM);

    // launch #1: weights -> fp16 on fork stream, overlapped with LN_in
    cudaEventRecord(g_hx.ev[0], 0);
    cudaStreamWaitEvent(g_hx.s2, g_hx.ev[0], 0);
    {
        int total4 = (NDI2 * DM + DM * DI) / 4;
        prep_w<<<(total4 + 255) / 256, 256, 0, g_hx.s2>>>(W_in, W_out);
    }
    cudaEventRecord(g_hx.ev[1], g_hx.s2);

    // launch #2: input LN -> fp16 (concurrent with prep_w)
    ln_kernel<1><<<NTOK, 256>>>(x, ln_in_g, ln_in_b, p_xnorm);

    // join before GEMM1
    cudaStreamWaitEvent(0, g_hx.ev[1], 0);

    // launch #3: GEMM1: [8192 x 3072] = LN(x) @ W_in^T, clip/split/tanh
    {
        dim3 grid(NDI2 / BN, NTOK / BM);   // (24, 64)
        mma_gemm<0><<<grid, 256, GEMM_SMEM>>>(p_xnorm, p_win, DM, p_xh, p_gh, nullptr);
    }

    // launch #4: chunked scan (ncu capture lands here)
    scan_kernel<<<(NB * NCHUNK * DI) / 128, 128>>>(A_log, Bm, Cm);

    // launch #5: GEMM2: [8192 x 1024] = y @ W_out^T, clip -> fp32
    {
        dim3 grid(DM / BN, NTOK / BM);     // (8, 64)
        mma_gemm<1><<<grid, 256, GEMM_SMEM>>>(p_y, p_wout, DI, nullptr, nullptr, p_out1);
    }

    // launch #6: output LN -> fp32 d_out
    ln_kernel<0><<<NTOK, 256>>>(p_out1, ln_out_g, ln_out_b, out);
}

// round 14
// speedup vs baseline: 4.4622x; 1.1446x over previous
#include <cuda_runtime.h>
#include <cuda_fp16.h>
#include <cstdint>

// ---------------------------------------------------------------------------
// SimplifiedMamba2Block on GB300 (sm_103a), compute_103-safe.
// Round 14: scan profile says latency-bound (occ 14.9%, issue 12.8%, nothing
// saturated) -> push chunk parallelism further: CHUNK=64, WARM=128 (error
// bound unchanged, 5*0.9^128 ~ 7e-6). 196608 threads = 4x warps vs R13 at
// 3x serial work (ALU floor ~40us equiv, still non-binding).
// GEMMs unchanged from R12/R13 (G1=177us, tensor pipe 47.8%).
// ---------------------------------------------------------------------------

#define NTOK   8192
#define DM     1024
#define DI     1536
#define DS     8
#define NDI2   3072
#define SEQ    2048
#define NB     4

#define CHUNK  64
#define WARM   128
#define NCHUNK (SEQ / CHUNK)     // 32

#define CLIP5(v) fminf(fmaxf((v), -5.0f), 5.0f)

// scratch (__device__ globals per allocation-free rule)
__device__ __half g_xnorm[NTOK * DM];    // LN(x), fp16
__device__ __half g_xh   [NTOK * DI];    // GEMM1 out ssm half, fp16
__device__ __half g_gh   [NTOK * DI];    // GEMM1 out tanh gate, fp16
__device__ __half g_y    [NTOK * DI];    // scan out y*gate, fp16 (GEMM2 A)
__device__ float  g_out1 [NTOK * DM];    // GEMM2 out, fp32
__device__ __half g_win  [NDI2 * DM];    // fp16 W_in
__device__ __half g_wout [DM * DI];      // fp16 W_out

// ======================= helpers ===========================================
__device__ __forceinline__ uint32_t smem_u32(const void* p) {
    uint32_t r;
    asm("{ .reg .u64 t; cvta.to.shared.u64 t, %1; cvt.u32.u64 %0, t; }"
        : "=r"(r) : "l"(p));
    return r;
}
__device__ __forceinline__ void cp_async16(uint32_t saddr, const void* gaddr) {
    asm volatile("cp.async.cg.shared.global [%0], [%1], 16;"
                 :: "r"(saddr), "l"(gaddr) : "memory");
}
#define CP_COMMIT() asm volatile("cp.async.commit_group;" ::: "memory")
#define CP_WAIT(n)  asm volatile("cp.async.wait_group %0;" :: "n"(n) : "memory")

__device__ __forceinline__ void mma_f16(float* d, const uint32_t* a, const uint32_t* b) {
    asm volatile(
        "mma.sync.aligned.m16n8k16.row.col.f32.f16.f16.f32 "
        "{%0,%1,%2,%3}, {%4,%5,%6,%7}, {%8,%9}, {%0,%1,%2,%3};"
        : "+f"(d[0]), "+f"(d[1]), "+f"(d[2]), "+f"(d[3])
        : "r"(a[0]), "r"(a[1]), "r"(a[2]), "r"(a[3]), "r"(b[0]), "r"(b[1]));
}
__device__ __forceinline__ void ldsm_x4(uint32_t* r, uint32_t addr) {
    asm volatile("ldmatrix.sync.aligned.m8n8.x4.shared.b16 {%0,%1,%2,%3}, [%4];"
                 : "=r"(r[0]), "=r"(r[1]), "=r"(r[2]), "=r"(r[3]) : "r"(addr));
}

// ======================= weight prep (fp32 -> fp16) =========================
__global__ __launch_bounds__(256) void prep_w(
    const float* __restrict__ win, const float* __restrict__ wout)
{
    const int n1 = (NDI2 * DM) / 4;
    const int n2 = (DM * DI) / 4;
    int i = blockIdx.x * blockDim.x + threadIdx.x;
    if (i < n1) {
        float4 v = ((const float4*)win)[i];
        __half2 h0 = __floats2half2_rn(v.x, v.y);
        __half2 h1 = __floats2half2_rn(v.z, v.w);
        uint2 u; u.x = *(uint32_t*)&h0; u.y = *(uint32_t*)&h1;
        ((uint2*)g_win)[i] = u;
    } else if (i < n1 + n2) {
        float4 v = ((const float4*)wout)[i - n1];
        __half2 h0 = __floats2half2_rn(v.x, v.y);
        __half2 h1 = __floats2half2_rn(v.z, v.w);
        uint2 u; u.x = *(uint32_t*)&h0; u.y = *(uint32_t*)&h1;
        ((uint2*)g_wout)[i - n1] = u;
    }
}

// ======================= LayerNorm =========================================
template<int HALF_OUT>
__global__ __launch_bounds__(256) void ln_kernel(
    const float* __restrict__ in, const float* __restrict__ g,
    const float* __restrict__ b, void* __restrict__ outv)
{
    __shared__ float s_sum[8], s_sq[8];
    int row = blockIdx.x;
    int tid = threadIdx.x;
    const float4 v = *(const float4*)(in + (size_t)row * DM + tid * 4);

    float sum = v.x + v.y + v.z + v.w;
    float sq  = v.x*v.x + v.y*v.y + v.z*v.z + v.w*v.w;
    #pragma unroll
    for (int o = 16; o > 0; o >>= 1) {
        sum += __shfl_xor_sync(0xffffffffu, sum, o);
        sq  += __shfl_xor_sync(0xffffffffu, sq , o);
    }
    int wid = tid >> 5, lid = tid & 31;
    if (lid == 0) { s_sum[wid] = sum; s_sq[wid] = sq; }
    __syncthreads();
    if (wid == 0) {
        float a = (lid < 8) ? s_sum[lid] : 0.f;
        float c = (lid < 8) ? s_sq [lid] : 0.f;
        #pragma unroll
        for (int o = 4; o > 0; o >>= 1) {
            a += __shfl_xor_sync(0xffffffffu, a, o);
            c += __shfl_xor_sync(0xffffffffu, c, o);
        }
        if (lid == 0) { s_sum[0] = a; s_sq[0] = c; }
    }
    __syncthreads();
    float mean = s_sum[0] * (1.0f / DM);
    float var  = s_sq[0] * (1.0f / DM) - mean * mean;
    float rstd = rsqrtf(var + 1e-5f);

    const float4 gv = *(const float4*)(g + tid * 4);
    const float4 bv = *(const float4*)(b + tid * 4);
    float4 o4;
    o4.x = (v.x - mean) * rstd * gv.x + bv.x;
    o4.y = (v.y - mean) * rstd * gv.y + bv.y;
    o4.z = (v.z - mean) * rstd * gv.z + bv.z;
    o4.w = (v.w - mean) * rstd * gv.w + bv.w;
    if (HALF_OUT) {
        __half2 h0 = __floats2half2_rn(o4.x, o4.y);
        __half2 h1 = __floats2half2_rn(o4.z, o4.w);
        uint2 u; u.x = *(uint32_t*)&h0; u.y = *(uint32_t*)&h1;
        *(uint2*)((__half*)outv + (size_t)row * DM + tid * 4) = u;
    } else {
        *(float4*)((float*)outv + (size_t)row * DM + tid * 4) = o4;
    }
}

// ======================= mma.sync f16 GEMM (128x128 tile, 2 CTA/SM) =========
// Unchanged from R12/R13 (G1 measured 177us, tensor pipe 47.8%).
// ---------------------------------------------------------------------------
#define BM      128
#define BN      128
#define STB     80u
#define A_BYTES (BM * STB)          // 10240
#define W_BYTES (BN * STB)          // 10240
#define STAGEB  (A_BYTES + W_BYTES) // 20480
#define NSTAGE  4
#define GEMM_SMEM (NSTAGE * STAGEB) // 81920

template<int MODE>
__global__ __launch_bounds__(256, 2) void mma_gemm(
    const __half* __restrict__ A, const __half* __restrict__ W, int K,
    __half* __restrict__ out0h, __half* __restrict__ out1h,
    float* __restrict__ out0f)
{
    extern __shared__ __align__(16) char dynsmem[];

    const int tid  = threadIdx.x;
    const int lane = tid & 31;
    const int wid  = tid >> 5;
    const int wm   = wid & 3;
    const int wn   = wid >> 2;
    const int bm   = blockIdx.y * BM;
    const int bn   = blockIdx.x * BN;

    float acc[2][8][4];
    #pragma unroll
    for (int mt = 0; mt < 2; mt++)
        #pragma unroll
        for (int nt = 0; nt < 8; nt++)
            #pragma unroll
            for (int f = 0; f < 4; f++) acc[mt][nt][f] = 0.f;

    const int frow = tid >> 2;
    const int fseg = tid & 3;
    const uint32_t sbase = smem_u32(dynsmem);
    const uint32_t fA = (uint32_t)frow * STB + (uint32_t)fseg * 16u;
    const __half* gA = A + (size_t)(bm + frow) * K + fseg * 8;
    const __half* gW = W + (size_t)(bn + frow) * K + fseg * 8;

    const int NC = K / 32;

    const uint32_t laneA = (uint32_t)(lane & 15) * STB + (uint32_t)(lane >> 4) * 16u;
    const uint32_t laneB = (uint32_t)(((lane >> 4) << 3) + (lane & 7)) * STB
                         + (uint32_t)((lane >> 3) & 1) * 16u;

    #pragma unroll
    for (int t = 0; t < 3; t++) {
        uint32_t base = sbase + t * STAGEB;
        const __half* at = gA + t * 32;
        const __half* wt = gW + t * 32;
        #pragma unroll
        for (int k = 0; k < 2; k++)
            cp_async16(base + fA + k * 64u * STB, at + (size_t)(k * 64) * K);
        #pragma unroll
        for (int k = 0; k < 2; k++)
            cp_async16(base + A_BYTES + fA + k * 64u * STB, wt + (size_t)(k * 64) * K);
        CP_COMMIT();
    }

    for (int c = 0; c < NC; c++) {
        if (c + 3 <= NC)      { CP_WAIT(2); }
        else if (c + 2 == NC) { CP_WAIT(1); }
        else                  { CP_WAIT(0); }
        __syncthreads();

        if (c + 3 < NC) {
            uint32_t base = sbase + ((c + 3) & 3) * STAGEB;
            const __half* at = gA + (c + 3) * 32;
            const __half* wt = gW + (c + 3) * 32;
            #pragma unroll
            for (int k = 0; k < 2; k++)
                cp_async16(base + fA + k * 64u * STB, at + (size_t)(k * 64) * K);
            #pragma unroll
            for (int k = 0; k < 2; k++)
                cp_async16(base + A_BYTES + fA + k * 64u * STB, wt + (size_t)(k * 64) * K);
            CP_COMMIT();
        }

        const uint32_t stA = sbase + (c & 3) * STAGEB;
        const uint32_t stW = stA + A_BYTES;

        #pragma unroll
        for (int ks = 0; ks < 2; ks++) {
            const uint32_t kb = (uint32_t)(ks * 32);
            uint32_t a[2][4], b[4][4];
            #pragma unroll
            for (int mt = 0; mt < 2; mt++)
                ldsm_x4(a[mt], stA + (uint32_t)(wm * 32 + mt * 16) * STB + kb + laneA);
            #pragma unroll
            for (int np = 0; np < 4; np++)
                ldsm_x4(b[np], stW + (uint32_t)(wn * 64 + np * 16) * STB + kb + laneB);
            #pragma unroll
            for (int mt = 0; mt < 2; mt++)
                #pragma unroll
                for (int nt = 0; nt < 8; nt++)
                    mma_f16(acc[mt][nt], a[mt], &b[nt >> 1][(nt & 1) * 2]);
        }
    }

    #pragma unroll
    for (int mt = 0; mt < 2; mt++) {
        #pragma unroll
        for (int nt = 0; nt < 8; nt++) {
            const int row0 = bm + wm * 32 + mt * 16 + (lane >> 2);
            const int col  = bn + wn * 64 + nt * 8 + (lane & 3) * 2;
            #pragma unroll
            for (int hh = 0; hh < 2; hh++) {
                const int row = row0 + hh * 8;
                float v0 = CLIP5(acc[mt][nt][hh * 2 + 0]);
                float v1 = CLIP5(acc[mt][nt][hh * 2 + 1]);
                if (MODE == 0) {
                    if (col < DI) {
                        *(__half2*)(out0h + (size_t)row * DI + col) =
                            __floats2half2_rn(v0, v1);
                    } else {
                        *(__half2*)(out1h + (size_t)row * DI + (col - DI)) =
                            __floats2half2_rn(tanhf(v0), tanhf(v1));
                    }
                } else {
                    *(float2*)(out0f + (size_t)row * DM + col) = make_float2(v0, v1);
                }
            }
        }
    }
}

// ======================= chunked SSM scan (CHUNK=64) ========================
// decay in [-0.9,-0.009]; clip is 1-Lipschitz => perturbations decay <=0.9^t.
// Each (b, chunk, channel) thread restarts h=0, runs up to WARM=128 discarded
// steps (error <= 5*0.9^128 ~ 7e-6; chunks with t0<=WARM warm exactly from
// t=0), then emits CHUNK outputs. 196608 threads (~10 warps/SMSP).
// ---------------------------------------------------------------------------
__global__ __launch_bounds__(128) void scan_kernel(
    const float* __restrict__ A_log, const float* __restrict__ Bm,
    const float* __restrict__ Cm)
{
    const int idx = blockIdx.x * blockDim.x + threadIdx.x; // 0..196607
    const int i   = idx % DI;
    const int bc  = idx / DI;          // 0..127
    const int b   = bc >> 5;           // batch
    const int c   = bc & 31;           // chunk

    float decay[DS], bs[DS], cs[DS], hreg[DS];
    #pragma unroll
    for (int s = 0; s < DS; s++) {
        float a = A_log[i * DS + s];
        a = fminf(fmaxf(a, -5.0f), 0.0f);
        float Av = -__expf(a);
        Av = fminf(fmaxf(Av, -2.0f), -0.01f);
        decay[s] = Av * 0.9f;
        bs[s] = Bm[i * DS + s] * 0.1f;
        cs[s] = Cm[i * DS + s];
        hreg[s] = 0.f;
    }

    const __half* __restrict__ xin  = g_xh + (size_t)b * SEQ * DI + i;
    const __half* __restrict__ gin  = g_gh + (size_t)b * SEQ * DI + i;
    __half*       __restrict__ yout = g_y  + (size_t)b * SEQ * DI + i;

    const int t0 = c * CHUNK;
    const int ts = (t0 >= WARM) ? (t0 - WARM) : 0;

    // warm-up: converge h, discard outputs (no gate loads, no y, no store)
    #pragma unroll 4
    for (int t = ts; t < t0; t++) {
        float x = __half2float(xin[(size_t)t * DI]);
        #pragma unroll
        for (int s = 0; s < DS; s++) {
            float hs = fmaf(hreg[s], decay[s], x * bs[s]);
            hreg[s] = CLIP5(hs);
        }
    }

    // emit chunk
    #pragma unroll 4
    for (int t = t0; t < t0 + CHUNK; t++) {
        float x  = __half2float(xin[(size_t)t * DI]);
        float gt = __half2float(gin[(size_t)t * DI]);
        float y = 0.f;
        #pragma unroll
        for (int s = 0; s < DS; s++) {
            float hs = fmaf(hreg[s], decay[s], x * bs[s]);
            hs = CLIP5(hs);
            hreg[s] = hs;
            y = fmaf(hs, cs[s], y);
        }
        y = CLIP5(y);
        yout[(size_t)t * DI] = __float2half_rn(y * gt);
    }
}

// ======================= streams (static init: before harness checkpoints) ==
struct HxStreams {
    cudaStream_t s2;
    cudaEvent_t ev[2];
    HxStreams() {
        cudaStreamCreateWithFlags(&s2, cudaStreamNonBlocking);
        for (int i = 0; i < 2; i++)
            cudaEventCreateWithFlags(&ev[i], cudaEventDisableTiming);
    }
};
static HxStreams g_hx;

// ======================= launch =============================================
extern "C" void kernel_launch(void* const* d_in, const int* in_sizes, int n_in,
                              void* d_out, int out_size)
{
    const float* x       = (const float*)d_in[0];
    const float* W_in    = (const float*)d_in[1];
    const float* W_out   = (const float*)d_in[2];
    const float* A_log   = (const float*)d_in[3];
    const float* Bm      = (const float*)d_in[4];
    const float* Cm      = (const float*)d_in[5];
    const float* ln_in_g = (const float*)d_in[6];
    const float* ln_in_b = (const float*)d_in[7];
    const float* ln_out_g= (const float*)d_in[8];
    const float* ln_out_b= (const float*)d_in[9];
    float* out = (float*)d_out;

    __half *p_xnorm, *p_xh, *p_gh, *p_y, *p_win, *p_wout;
    float *p_out1;
    cudaGetSymbolAddress((void**)&p_xnorm, g_xnorm);
    cudaGetSymbolAddress((void**)&p_xh   , g_xh);
    cudaGetSymbolAddress((void**)&p_gh   , g_gh);
    cudaGetSymbolAddress((void**)&p_y    , g_y);
    cudaGetSymbolAddress((void**)&p_out1 , g_out1);
    cudaGetSymbolAddress((void**)&p_win  , g_win);
    cudaGetSymbolAddress((void**)&p_wout , g_wout);

    cudaFuncSetAttribute(mma_gemm<0>, cudaFuncAttributeMaxDynamicSharedMemorySize, GEMM_SMEM);
    cudaFuncSetAttribute(mma_gemm<1>, cudaFuncAttributeMaxDynamicSharedMemorySize, GEMM_SMEM);

    // launch #1: weights -> fp16 on fork stream, overlapped with LN_in
    cudaEventRecord(g_hx.ev[0], 0);
    cudaStreamWaitEvent(g_hx.s2, g_hx.ev[0], 0);
    {
        int total4 = (NDI2 * DM + DM * DI) / 4;
        prep_w<<<(total4 + 255) / 256, 256, 0, g_hx.s2>>>(W_in, W_out);
    }
    cudaEventRecord(g_hx.ev[1], g_hx.s2);

    // launch #2: input LN -> fp16 (concurrent with prep_w)
    ln_kernel<1><<<NTOK, 256>>>(x, ln_in_g, ln_in_b, p_xnorm);

    // join before GEMM1
    cudaStreamWaitEvent(0, g_hx.ev[1], 0);

    // launch #3: GEMM1: [8192 x 3072] = LN(x) @ W_in^T, clip/split/tanh
    {
        dim3 grid(NDI2 / BN, NTOK / BM);   // (24, 64)
        mma_gemm<0><<<grid, 256, GEMM_SMEM>>>(p_xnorm, p_win, DM, p_xh, p_gh, nullptr);
    }

    // launch #4: chunked scan (ncu capture lands here)
    scan_kernel<<<(NB * NCHUNK * DI) / 128, 128>>>(A_log, Bm, Cm);

    // launch #5: GEMM2: [8192 x 1024] = y @ W_out^T, clip -> fp32
    {
        dim3 grid(DM / BN, NTOK / BM);     // (8, 64)
        mma_gemm<1><<<grid, 256, GEMM_SMEM>>>(p_y, p_wout, DI, nullptr, nullptr, p_out1);
    }

    // launch #6: output LN -> fp32 d_out
    ln_kernel<0><<<NTOK, 256>>>(p_out1, ln_out_g, ln_out_b, out);
}